// round 11
// baseline (speedup 1.0000x reference)
#include <cuda_runtime.h>
#include <cuda_bf16.h>
#include <mma.h>
#include <cstdint>

using namespace nvcuda;

#define H   12
#define NN  2048
#define DD  128
#define BM  64
#define QG  32          // NN/BM
#define IC  192         // indices_count = 64*round(0.1*2048/64)
#define WHALF 153       // int(0.15*2048)//2
#define SCALE 0.08838834764831843f
#define KSPLIT 3        // kD split factor
#define JSPLIT 4        // kAwm key-range split

// ---------------- scratch (device globals; no allocations allowed) ----------
__device__ float g_P[(size_t)H * NN * NN];   // exp(q.kT * scale), 201 MB
__device__ float g_lp[JSPLIT * H * NN];      // partial rowsums (jh quarters)
__device__ float g_bs[H * QG * NN];          // colsum of probs per group
__device__ int   g_idx[(size_t)H * QG * NN]; // selected key indices (compact)
__device__ int   g_cnt[H * QG];
__device__ float g_accD[(size_t)H * QG * KSPLIT * BM * DD];  // kD partials, 38MB
__device__ float g_lsD[H * QG * KSPLIT * BM];

// ---------------- threefry2x32 (JAX-compatible, 20 rounds) ------------------
__host__ __device__ __forceinline__ void tf2x32(uint32_t ka, uint32_t kb,
                                                uint32_t x0, uint32_t x1,
                                                uint32_t& o0, uint32_t& o1) {
    uint32_t ks0 = ka, ks1 = kb, ks2 = ka ^ kb ^ 0x1BD11BDAu;
    x0 += ks0; x1 += ks1;
    const int R0[4] = {13, 15, 26, 6};
    const int R1[4] = {17, 29, 16, 24};
    uint32_t ks[3] = {ks0, ks1, ks2};
#pragma unroll
    for (int g = 0; g < 5; ++g) {
        const int* R = (g & 1) ? R1 : R0;
#pragma unroll
        for (int r = 0; r < 4; ++r) {
            x0 += x1;
            x1 = (x1 << R[r]) | (x1 >> (32 - R[r]));
            x1 ^= x0;
        }
        x0 += ks[(g + 1) % 3];
        x1 += ks[(g + 2) % 3] + (uint32_t)(g + 1);
    }
    o0 = x0; o1 = x1;
}

__device__ __forceinline__ uint32_t tf_fold(uint32_t ka, uint32_t kb,
                                            uint32_t x0, uint32_t x1) {
    uint32_t a, b;
    tf2x32(ka, kb, x0, x1, a, b);
    return a ^ b;   // partitionable 32-bit fold
}

// bf16x2 pack: low 16 bits = x0 (lower element), high 16 bits = x1
__device__ __forceinline__ uint32_t pack_bf16x2(float x0, float x1) {
    uint32_t r;
    asm("cvt.rn.bf16x2.f32 %0, %1, %2;" : "=r"(r) : "f"(x1), "f"(x0));
    return r;
}

// =============================================================================
// kAwm: P = exp(QK^T * scale) via wmma bf16 split-GEMM (hi/lo decomposition)
//       + deterministic PARTIAL row sums -> g_lp[jh]
// grid (it=32, h=12, jh=4), 256 threads (8 warps), ~68.5 KB dyn smem, 3 CTA/SM
// C tile is aliased onto the B region (dead between MMA end and next B load).
// =============================================================================

#define ASTR 136   // bf16 elements per A row (128 + 8 pad)
#define BSTR 136   // bf16 elements per B row
#define CSTR 68    // f32 elements per C row (64 + 4 pad)

#define NA64 (64 * ASTR)                 // one 64-row bf16 tile
#define SMEM_AWM (4 * NA64 * 2 + 512)    // 70144 B

__global__ __launch_bounds__(256, 3) void kAwm(const float* __restrict__ q,
                                               const float* __restrict__ k) {
    extern __shared__ char smemraw[];
    __nv_bfloat16* sAhi = reinterpret_cast<__nv_bfloat16*>(smemraw);
    __nv_bfloat16* sAlo = sAhi + NA64;
    __nv_bfloat16* sBhi = sAlo + NA64;
    __nv_bfloat16* sBlo = sBhi + NA64;
    float* sC = reinterpret_cast<float*>(sBhi);    // ALIAS: C over Bhi (17408 B)
    float* sRS = reinterpret_cast<float*>(sBlo + NA64);   // 128 floats

    const int t = threadIdx.x;
    const int lane = t & 31;
    const int it = blockIdx.x, h = blockIdx.y, jh = blockIdx.z;
    const int w = t >> 5;
    const int wm = w >> 1;       // 0..3 -> rows wm*16..+15
    const int wn = w & 1;        // 0..1 -> cols wn*32..+31
    const int r16 = lane >> 1;   // 0..15 row within warp tile
    const int ch = (lane & 1) * 16;   // 16-col chunk within warp's 32 cols

    // ---- load Q tile (64 rows x 128 f32) -> bf16 hi/lo ----------------------
    {
        const float2* qg = reinterpret_cast<const float2*>(
            q + ((size_t)h * NN + (size_t)it * 64) * DD);
#pragma unroll
        for (int e = t; e < 64 * 64; e += 256) {
            int r = e >> 6, kp = e & 63;
            float2 x = qg[e];
            uint32_t hp = pack_bf16x2(x.x, x.y);
            float h0 = __uint_as_float(hp << 16);
            float h1 = __uint_as_float(hp & 0xFFFF0000u);
            uint32_t lp = pack_bf16x2(x.x - h0, x.y - h1);
            int off = r * ASTR + 2 * kp;
            *reinterpret_cast<uint32_t*>(sAhi + off) = hp;
            *reinterpret_cast<uint32_t*>(sAlo + off) = lp;
        }
    }

    float rsum = 0.f;
    const int rowbase = h * NN + it * 64;

    const int jt0 = jh * (QG / JSPLIT);
    for (int jtt = 0; jtt < QG / JSPLIT; ++jtt) {
        const int jt = jt0 + jtt;
        __syncthreads();   // all epilogue reads of C(=Bhi) done before overwrite
        // ---- load K tile (64 keys x 128 dims) -> bf16 hi/lo -----------------
        const float2* kg = reinterpret_cast<const float2*>(
            k + ((size_t)h * NN + (size_t)jt * 64) * DD);
#pragma unroll
        for (int e = t; e < 64 * 64; e += 256) {
            int r = e >> 6, kp = e & 63;
            float2 x = kg[e];
            uint32_t hp = pack_bf16x2(x.x, x.y);
            float h0 = __uint_as_float(hp << 16);
            float h1 = __uint_as_float(hp & 0xFFFF0000u);
            uint32_t lp = pack_bf16x2(x.x - h0, x.y - h1);
            int off = r * BSTR + 2 * kp;
            *reinterpret_cast<uint32_t*>(sBhi + off) = hp;
            *reinterpret_cast<uint32_t*>(sBlo + off) = lp;
        }
        __syncthreads();

        // ---- 3-pass split GEMM into fp32 accumulators -----------------------
        wmma::fragment<wmma::accumulator, 16, 16, 16, float> c0, c1;
        wmma::fill_fragment(c0, 0.f);
        wmma::fill_fragment(c1, 0.f);

        const __nv_bfloat16* Ap[3] = {sAhi, sAhi, sAlo};
        const __nv_bfloat16* Bp[3] = {sBhi, sBlo, sBhi};

#pragma unroll
        for (int p = 0; p < 3; ++p) {
            const __nv_bfloat16* Ab = Ap[p] + (wm * 16) * ASTR;
            const __nv_bfloat16* Bb = Bp[p] + (wn * 32) * BSTR;
#pragma unroll
            for (int kk = 0; kk < 8; ++kk) {
                wmma::fragment<wmma::matrix_a, 16, 16, 16, __nv_bfloat16,
                               wmma::row_major> a0;
                wmma::fragment<wmma::matrix_b, 16, 16, 16, __nv_bfloat16,
                               wmma::col_major> b0, b1;
                wmma::load_matrix_sync(a0, Ab + kk * 16, ASTR);
                wmma::load_matrix_sync(b0, Bb + kk * 16, BSTR);
                wmma::load_matrix_sync(b1, Bb + 16 * BSTR + kk * 16, BSTR);
                wmma::mma_sync(c0, a0, b0, c0);
                wmma::mma_sync(c1, a0, b1, c1);
            }
        }

        // ---- all B reads done -> C may overwrite B region -------------------
        __syncthreads();
        float* Cb = sC + (wm * 16) * CSTR + wn * 32;
        wmma::store_matrix_sync(Cb, c0, CSTR, wmma::mem_row_major);
        wmma::store_matrix_sync(Cb + 16, c1, CSTR, wmma::mem_row_major);
        __syncwarp();

        // ---- per-warp epilogue: exp, rowsum, store --------------------------
        {
            const float* crow = sC + (wm * 16 + r16) * CSTR + wn * 32 + ch;
            float* orow = g_P + (size_t)(rowbase + wm * 16 + r16) * NN
                        + jt * 64 + wn * 32 + ch;
#pragma unroll
            for (int c0i = 0; c0i < 16; c0i += 4) {
                float4 s = *reinterpret_cast<const float4*>(crow + c0i);
                float f0 = __expf(s.x * SCALE);
                float f1 = __expf(s.y * SCALE);
                float f2 = __expf(s.z * SCALE);
                float f3 = __expf(s.w * SCALE);
                rsum += (f0 + f1) + (f2 + f3);
                *reinterpret_cast<float4*>(orow + c0i) =
                    make_float4(f0, f1, f2, f3);
            }
        }
    }

    // ---- combine row sums: lane pairs -> warp halves -> block ---------------
    rsum += __shfl_xor_sync(0xFFFFFFFFu, rsum, 1);   // both 16-col chunks
    __syncthreads();
    if ((lane & 1) == 0) sRS[wn * 64 + wm * 16 + r16] = rsum;
    __syncthreads();
    if (t < 64)
        g_lp[jh * (H * NN) + rowbase + t] = sRS[t] + sRS[64 + t];
}

// ---------------- kernel B: bs[h][g][j] = sum_i P[i][j]/l_i -----------------
// grid (H*QG, 2), 256 threads, 4 j per thread (float4)
__global__ __launch_bounds__(256) void kB() {
    const int hg = blockIdx.x;
    const int j0 = blockIdx.y * 1024 + threadIdx.x * 4;
    const int h = hg / QG, g = hg % QG;
    __shared__ float sl[BM];
    if (threadIdx.x < BM) {
        int row = h * NN + g * BM + threadIdx.x;
        float l = 0.f;
#pragma unroll
        for (int p = 0; p < JSPLIT; ++p) l += g_lp[p * (H * NN) + row];
        sl[threadIdx.x] = 1.0f / l;
    }
    __syncthreads();
    const float* Pb = g_P + ((size_t)h * NN + (size_t)g * BM) * NN + j0;
    float4 acc = make_float4(0.f, 0.f, 0.f, 0.f);
#pragma unroll 8
    for (int i = 0; i < BM; ++i) {
        float4 x = *reinterpret_cast<const float4*>(Pb + (size_t)i * NN);
        float w = sl[i];
        acc.x += x.x * w; acc.y += x.y * w;
        acc.z += x.z * w; acc.w += x.w * w;
    }
    *reinterpret_cast<float4*>(g_bs + (size_t)hg * NN + j0) = acc;
}

// ---------------- block scan helper -----------------------------------------
__device__ __forceinline__ int blockScanExcl(int val, int t, int* wsum, int& total) {
    __syncthreads();
    int lane = t & 31, w = t >> 5;
    int x = val;
#pragma unroll
    for (int o = 1; o < 32; o <<= 1) {
        int y = __shfl_up_sync(0xFFFFFFFFu, x, o);
        if (lane >= o) x += y;
    }
    if (lane == 31) wsum[w] = x;
    __syncthreads();
    if (t < 8) {
        int y = wsum[t];
#pragma unroll
        for (int o = 1; o < 8; o <<= 1) {
            int z = __shfl_up_sync(0xFFu, y, o);
            if (t >= o) y += z;
        }
        wsum[t] = y;
    }
    __syncthreads();
    int base = (w > 0) ? wsum[w - 1] : 0;
    total = wsum[7];
    return base + x - val;
}

// ---------------- kernel C: top-k select + static + random -> index list ----
__global__ __launch_bounds__(256) void kC(uint32_t k1a, uint32_t k1b,
                                          uint32_t k2a, uint32_t k2b) {
    __shared__ uint32_t su[NN];
    __shared__ int hist[256];
    __shared__ int wsum[8];
    __shared__ int s_digit, s_rem;
    const int hg = blockIdx.x;
    const int g = hg % QG;
    const int t = threadIdx.x;

    const float* bs = g_bs + (size_t)hg * NN;
    for (int e = t; e < NN; e += 256) su[e] = __float_as_uint(bs[e]);
    __syncthreads();

    uint32_t pre = 0, preMask = 0;
    int rem = IC;
    for (int shift = 24; shift >= 0; shift -= 8) {
        hist[t] = 0;
        __syncthreads();
#pragma unroll
        for (int ee = 0; ee < 8; ++ee) {
            uint32_t u = su[t * 8 + ee];
            if ((u & preMask) == pre) atomicAdd(&hist[(u >> shift) & 255], 1);
        }
        __syncthreads();
        if (t == 0) {
            int cum = 0, d = 255;
            for (; d > 0; --d) {
                int c = hist[d];
                if (cum + c >= rem) break;
                cum += c;
            }
            s_digit = d;
            s_rem = rem - cum;
        }
        __syncthreads();
        pre |= ((uint32_t)s_digit) << shift;
        preMask |= 0xFFu << shift;
        rem = s_rem;
        __syncthreads();
    }
    const uint32_t v = pre;
    const int need_eq = rem;

    // rank among equals (ascending index, matching lax.top_k stability)
    int eqc = 0;
#pragma unroll
    for (int ee = 0; ee < 8; ++ee) eqc += (su[t * 8 + ee] == v) ? 1 : 0;
    int dummy;
    int eq_base = blockScanExcl(eqc, t, wsum, dummy);

    const int lo = g * BM + BM / 2 - WHALF;
    const int hi = g * BM + BM / 2 + WHALF;

    unsigned char lf[8];
    int fc = 0, eqrun = eq_base;
#pragma unroll
    for (int ee = 0; ee < 8; ++ee) {
        int j = t * 8 + ee;
        uint32_t u = su[j];
        bool topk = (u > v);
        if (u == v) { topk = topk || (eqrun < need_eq); ++eqrun; }
        bool stat = (j >= lo) && (j < hi);
        uint32_t ilin = (uint32_t)hg * NN + (uint32_t)j;
        uint32_t hb = tf_fold(k1a, k1b, 0u, ilin);
        uint32_t lb = tf_fold(k2a, k2b, 0u, ilin);
        bool rnd = (((hb % 100u) * 96u + (lb % 100u)) % 100u) == 0u;
        bool f = topk || stat || rnd;
        lf[ee] = f ? 1 : 0;
        fc += lf[ee];
    }
    int tot;
    int base = blockScanExcl(fc, t, wsum, tot);
    int* dst = g_idx + (size_t)hg * NN;
    int p = base;
#pragma unroll
    for (int ee = 0; ee < 8; ++ee)
        if (lf[ee]) dst[p++] = t * 8 + ee;
    if (t == 0) g_cnt[hg] = tot;
}

// ---------------- kernel D: sparse PV partials (split-K over key tiles) -----
// grid (384, KSPLIT), 256 thr, 49.4 KB smem, <=64 regs -> 4 CTA/SM.
__global__ __launch_bounds__(256, 4) void kD(const float* __restrict__ vin) {
    extern __shared__ float dynD[];
    float* sV = dynD;                    // 64*128
    float* sP = dynD + 64 * 128;         // 64*64 (broadcast reads: no pad)
    int* sIdx = reinterpret_cast<int*>(dynD + 64 * 128 + 64 * 64);

    const int hg = blockIdx.x;
    const int s = blockIdx.y;
    const int h = hg / QG, g = hg % QG;
    const int t = threadIdx.x;
    const int lane = t & 31;
    const int tg = t >> 5;               // warp id 0..7 -> rows tg*8..tg*8+7
    int cnt = g_cnt[hg];
    if (cnt < 1) cnt = 1;
    const int* idx = g_idx + (size_t)hg * NN;

    float acc[8][4];
#pragma unroll
    for (int r = 0; r < 8; ++r) {
        acc[r][0] = 0.f; acc[r][1] = 0.f; acc[r][2] = 0.f; acc[r][3] = 0.f;
    }
    float ls[8];
#pragma unroll
    for (int r = 0; r < 8; ++r) ls[r] = 0.f;

    const float* vb = vin + (size_t)h * NN * DD;
    const size_t prow0 = ((size_t)h * NN + (size_t)g * BM) * NN;

    for (int j0 = s * 64; j0 < cnt; j0 += KSPLIT * 64) {
        const int tl = min(64, cnt - j0);
        __syncthreads();
        if (t < 64) sIdx[t] = (t < tl) ? idx[j0 + t] : 0;
        __syncthreads();
        // gather P tile (zero padded columns)
        for (int e = t; e < 64 * 64; e += 256) {
            int ii = e >> 6, jj = e & 63;
            sP[ii * 64 + jj] = (jj < tl) ? g_P[prow0 + (size_t)ii * NN + sIdx[jj]] : 0.f;
        }
        // gather V tile rows
        for (int e = t; e < 64 * 32; e += 256) {
            int jj = e >> 5, c = e & 31;
            float4 val;
            if (jj < tl) val = reinterpret_cast<const float4*>(vb + (size_t)sIdx[jj] * DD)[c];
            else         val = make_float4(0.f, 0.f, 0.f, 0.f);
            reinterpret_cast<float4*>(sV)[jj * 32 + c] = val;
        }
        __syncthreads();

        const float* sProw = sP + tg * 8 * 64;
#pragma unroll 2
        for (int jj = 0; jj < 64; ++jj) {
            float4 v4 = *reinterpret_cast<const float4*>(sV + jj * 128 + lane * 4);
#pragma unroll
            for (int r = 0; r < 8; ++r) {
                float p = sProw[r * 64 + jj];     // broadcast across warp
                ls[r] += p;
                acc[r][0] += p * v4.x;
                acc[r][1] += p * v4.y;
                acc[r][2] += p * v4.z;
                acc[r][3] += p * v4.w;
            }
        }
    }

    float* ab = g_accD + ((size_t)hg * KSPLIT + s) * (BM * DD);
    float* lb = g_lsD + (hg * KSPLIT + s) * BM;
#pragma unroll
    for (int r = 0; r < 8; ++r) {
        int row = tg * 8 + r;
        *reinterpret_cast<float4*>(ab + row * DD + lane * 4) =
            make_float4(acc[r][0], acc[r][1], acc[r][2], acc[r][3]);
        if (lane == 0) lb[row] = ls[r];
    }
}

// ---------------- kernel E: combine kD partials + cache add -----------------
// grid 384, 256 thr. thread t: row = t>>2, 32-dim segment (t&3)*32.
__global__ __launch_bounds__(256) void kE(const float* __restrict__ cache,
                                          float* __restrict__ out) {
    const int hg = blockIdx.x;
    const int h = hg / QG, g = hg % QG;
    const int t = threadIdx.x;
    const int row = t >> 2;
    const int seg = (t & 3) * 32;

    const float* lb = g_lsD + hg * KSPLIT * BM;
    float lsum = 0.f;
#pragma unroll
    for (int s = 0; s < KSPLIT; ++s) lsum += lb[s * BM + row];
    const float inv = 1.0f / lsum;

    const float* ab = g_accD + (size_t)hg * KSPLIT * (BM * DD) + row * DD + seg;
    const size_t grow = (size_t)h * NN + (size_t)g * BM + row;
    const float* cr = cache + grow * DD + seg;
    float* orow = out + grow * DD + seg;

#pragma unroll
    for (int c = 0; c < 32; c += 4) {
        float4 a0 = *reinterpret_cast<const float4*>(ab + c);
        float4 a1 = *reinterpret_cast<const float4*>(ab + BM * DD + c);
        float4 a2 = *reinterpret_cast<const float4*>(ab + 2 * BM * DD + c);
        float4 cv = *reinterpret_cast<const float4*>(cr + c);
        float4 ov;
        ov.x = cv.x + (a0.x + a1.x + a2.x) * inv;
        ov.y = cv.y + (a0.y + a1.y + a2.y) * inv;
        ov.z = cv.z + (a0.z + a1.z + a2.z) * inv;
        ov.w = cv.w + (a0.w + a1.w + a2.w) * inv;
        *reinterpret_cast<float4*>(orow + c) = ov;
    }
}

// ---------------- launch -----------------------------------------------------
extern "C" void kernel_launch(void* const* d_in, const int* in_sizes, int n_in,
                              void* d_out, int out_size) {
    const float* q     = (const float*)d_in[0];
    const float* k     = (const float*)d_in[1];
    const float* v     = (const float*)d_in[2];
    const float* cache = (const float*)d_in[3];
    float* out = (float*)d_out;

    (void)in_sizes; (void)n_in; (void)out_size;

    cudaFuncSetAttribute(kAwm, cudaFuncAttributeMaxDynamicSharedMemorySize, SMEM_AWM);
    cudaFuncSetAttribute(kD, cudaFuncAttributeMaxDynamicSharedMemorySize, 49408);

    // JAX key(1) = (0,1); partitionable foldlike split -> k1, k2
    uint32_t k1a, k1b, k2a, k2b;
    tf2x32(0u, 1u, 0u, 0u, k1a, k1b);
    tf2x32(0u, 1u, 0u, 1u, k2a, k2b);

    dim3 gA(32, H, JSPLIT);
    kAwm<<<gA, 256, SMEM_AWM>>>(q, k);
    dim3 gB(H * QG, 2);
    kB<<<gB, 256>>>();
    kC<<<H * QG, 256>>>(k1a, k1b, k2a, k2b);
    dim3 gD(H * QG, KSPLIT);
    kD<<<gD, 256, 49408>>>(v);
    kE<<<H * QG, 256>>>(cache, out);
}

// round 12
// speedup vs baseline: 1.3245x; 1.3245x over previous
#include <cuda_runtime.h>
#include <cuda_bf16.h>
#include <mma.h>
#include <cstdint>

using namespace nvcuda;

#define H   12
#define NN  2048
#define DD  128
#define BM  64
#define QG  32          // NN/BM
#define IC  192         // indices_count = 64*round(0.1*2048/64)
#define WHALF 153       // int(0.15*2048)//2
#define SCALE 0.08838834764831843f
#define KSPLIT 3        // kD split factor
#define JSPLIT 2        // kAwm key-range split

// ---------------- scratch (device globals; no allocations allowed) ----------
__device__ float g_P[(size_t)H * NN * NN];   // exp(q.kT * scale), 201 MB
__device__ float g_lp[JSPLIT * H * NN];      // partial rowsums (jh halves)
__device__ float g_bs[H * QG * NN];          // colsum of probs per group
__device__ int   g_idx[(size_t)H * QG * NN]; // selected key indices (compact)
__device__ int   g_cnt[H * QG];
__device__ float g_accD[(size_t)H * QG * KSPLIT * BM * DD];  // kD partials, 38MB
__device__ float g_lsD[H * QG * KSPLIT * BM];

// ---------------- threefry2x32 (JAX-compatible, 20 rounds) ------------------
__host__ __device__ __forceinline__ void tf2x32(uint32_t ka, uint32_t kb,
                                                uint32_t x0, uint32_t x1,
                                                uint32_t& o0, uint32_t& o1) {
    uint32_t ks0 = ka, ks1 = kb, ks2 = ka ^ kb ^ 0x1BD11BDAu;
    x0 += ks0; x1 += ks1;
    const int R0[4] = {13, 15, 26, 6};
    const int R1[4] = {17, 29, 16, 24};
    uint32_t ks[3] = {ks0, ks1, ks2};
#pragma unroll
    for (int g = 0; g < 5; ++g) {
        const int* R = (g & 1) ? R1 : R0;
#pragma unroll
        for (int r = 0; r < 4; ++r) {
            x0 += x1;
            x1 = (x1 << R[r]) | (x1 >> (32 - R[r]));
            x1 ^= x0;
        }
        x0 += ks[(g + 1) % 3];
        x1 += ks[(g + 2) % 3] + (uint32_t)(g + 1);
    }
    o0 = x0; o1 = x1;
}

__device__ __forceinline__ uint32_t tf_fold(uint32_t ka, uint32_t kb,
                                            uint32_t x0, uint32_t x1) {
    uint32_t a, b;
    tf2x32(ka, kb, x0, x1, a, b);
    return a ^ b;   // partitionable 32-bit fold
}

// bf16x2 pack: low 16 bits = x0 (lower element), high 16 bits = x1
__device__ __forceinline__ uint32_t pack_bf16x2(float x0, float x1) {
    uint32_t r;
    asm("cvt.rn.bf16x2.f32 %0, %1, %2;" : "=r"(r) : "f"(x1), "f"(x0));
    return r;
}

// =============================================================================
// kAwm: P = exp(QK^T * scale) via wmma bf16 split-GEMM (hi/lo decomposition)
//       + deterministic PARTIAL row sums -> g_lp[jh]
// grid (it=32, h=12, jh=2), 256 threads (8 warps), ~87.6 KB dyn smem, 2 CTA/SM
// (Round-9 configuration — measured-good. Do NOT cap registers below natural.)
// =============================================================================

#define ASTR 136   // bf16 elements per A row (128 + 8 pad)
#define BSTR 136   // bf16 elements per B row
#define CSTR 68    // f32 elements per C row (64 + 4 pad)

#define NA64 (64 * ASTR)                 // one 64-row bf16 tile
#define SMEM_AWM (4 * NA64 * 2 + 64 * CSTR * 4 + 512)   // 87552 B

__global__ __launch_bounds__(256, 2) void kAwm(const float* __restrict__ q,
                                               const float* __restrict__ k) {
    extern __shared__ char smemraw[];
    __nv_bfloat16* sAhi = reinterpret_cast<__nv_bfloat16*>(smemraw);
    __nv_bfloat16* sAlo = sAhi + NA64;
    __nv_bfloat16* sBhi = sAlo + NA64;
    __nv_bfloat16* sBlo = sBhi + NA64;
    float* sC = reinterpret_cast<float*>(sBlo + NA64);
    float* sRS = sC + 64 * CSTR;          // 128 floats

    const int t = threadIdx.x;
    const int lane = t & 31;
    const int it = blockIdx.x, h = blockIdx.y, jh = blockIdx.z;
    const int w = t >> 5;
    const int wm = w >> 1;       // 0..3 -> rows wm*16..+15
    const int wn = w & 1;        // 0..1 -> cols wn*32..+31
    const int r16 = lane >> 1;   // 0..15 row within warp tile
    const int ch = (lane & 1) * 16;   // 16-col chunk within warp's 32 cols

    // ---- load Q tile (64 rows x 128 f32) -> bf16 hi/lo ----------------------
    {
        const float2* qg = reinterpret_cast<const float2*>(
            q + ((size_t)h * NN + (size_t)it * 64) * DD);
#pragma unroll
        for (int e = t; e < 64 * 64; e += 256) {
            int r = e >> 6, kp = e & 63;
            float2 x = qg[e];
            uint32_t hp = pack_bf16x2(x.x, x.y);
            float h0 = __uint_as_float(hp << 16);
            float h1 = __uint_as_float(hp & 0xFFFF0000u);
            uint32_t lp = pack_bf16x2(x.x - h0, x.y - h1);
            int off = r * ASTR + 2 * kp;
            *reinterpret_cast<uint32_t*>(sAhi + off) = hp;
            *reinterpret_cast<uint32_t*>(sAlo + off) = lp;
        }
    }

    float rsum = 0.f;
    const int rowbase = h * NN + it * 64;

    const int jt0 = jh * (QG / JSPLIT);
    for (int jtt = 0; jtt < QG / JSPLIT; ++jtt) {
        const int jt = jt0 + jtt;
        __syncthreads();   // all warps done reading previous B before overwrite
        // ---- load K tile (64 keys x 128 dims) -> bf16 hi/lo -----------------
        const float2* kg = reinterpret_cast<const float2*>(
            k + ((size_t)h * NN + (size_t)jt * 64) * DD);
#pragma unroll
        for (int e = t; e < 64 * 64; e += 256) {
            int r = e >> 6, kp = e & 63;
            float2 x = kg[e];
            uint32_t hp = pack_bf16x2(x.x, x.y);
            float h0 = __uint_as_float(hp << 16);
            float h1 = __uint_as_float(hp & 0xFFFF0000u);
            uint32_t lp = pack_bf16x2(x.x - h0, x.y - h1);
            int off = r * BSTR + 2 * kp;
            *reinterpret_cast<uint32_t*>(sBhi + off) = hp;
            *reinterpret_cast<uint32_t*>(sBlo + off) = lp;
        }
        __syncthreads();

        // ---- 3-pass split GEMM into fp32 accumulators -----------------------
        wmma::fragment<wmma::accumulator, 16, 16, 16, float> c0, c1;
        wmma::fill_fragment(c0, 0.f);
        wmma::fill_fragment(c1, 0.f);

        const __nv_bfloat16* Ap[3] = {sAhi, sAhi, sAlo};
        const __nv_bfloat16* Bp[3] = {sBhi, sBlo, sBhi};

#pragma unroll
        for (int p = 0; p < 3; ++p) {
            const __nv_bfloat16* Ab = Ap[p] + (wm * 16) * ASTR;
            const __nv_bfloat16* Bb = Bp[p] + (wn * 32) * BSTR;
#pragma unroll
            for (int kk = 0; kk < 8; ++kk) {
                wmma::fragment<wmma::matrix_a, 16, 16, 16, __nv_bfloat16,
                               wmma::row_major> a0;
                wmma::fragment<wmma::matrix_b, 16, 16, 16, __nv_bfloat16,
                               wmma::col_major> b0, b1;
                wmma::load_matrix_sync(a0, Ab + kk * 16, ASTR);
                wmma::load_matrix_sync(b0, Bb + kk * 16, BSTR);
                wmma::load_matrix_sync(b1, Bb + 16 * BSTR + kk * 16, BSTR);
                wmma::mma_sync(c0, a0, b0, c0);
                wmma::mma_sync(c1, a0, b1, c1);
            }
        }

        // ---- store C (per-warp private region), per-warp epilogue -----------
        float* Cb = sC + (wm * 16) * CSTR + wn * 32;
        wmma::store_matrix_sync(Cb, c0, CSTR, wmma::mem_row_major);
        wmma::store_matrix_sync(Cb + 16, c1, CSTR, wmma::mem_row_major);
        __syncwarp();

        {
            const float* crow = sC + (wm * 16 + r16) * CSTR + wn * 32 + ch;
            float* orow = g_P + (size_t)(rowbase + wm * 16 + r16) * NN
                        + jt * 64 + wn * 32 + ch;
#pragma unroll
            for (int c0i = 0; c0i < 16; c0i += 4) {
                float4 s = *reinterpret_cast<const float4*>(crow + c0i);
                float f0 = __expf(s.x * SCALE);
                float f1 = __expf(s.y * SCALE);
                float f2 = __expf(s.z * SCALE);
                float f3 = __expf(s.w * SCALE);
                rsum += (f0 + f1) + (f2 + f3);
                *reinterpret_cast<float4*>(orow + c0i) =
                    make_float4(f0, f1, f2, f3);
            }
        }
        // top-of-loop __syncthreads orders C reuse (per-warp private anyway)
    }

    // ---- combine row sums: lane pairs -> warp halves -> block ---------------
    rsum += __shfl_xor_sync(0xFFFFFFFFu, rsum, 1);   // both 16-col chunks
    __syncthreads();                                  // sC done, reuse region
    if ((lane & 1) == 0) sRS[wn * 64 + wm * 16 + r16] = rsum;
    __syncthreads();
    if (t < 64)
        g_lp[jh * (H * NN) + rowbase + t] = sRS[t] + sRS[64 + t];
}

// ---------------- kernel B: bs[h][g][j] = sum_i P[i][j]/l_i -----------------
// grid (H*QG, 2), 256 threads, 4 j per thread (float4)
__global__ __launch_bounds__(256) void kB() {
    const int hg = blockIdx.x;
    const int j0 = blockIdx.y * 1024 + threadIdx.x * 4;
    const int h = hg / QG, g = hg % QG;
    __shared__ float sl[BM];
    if (threadIdx.x < BM) {
        int row = h * NN + g * BM + threadIdx.x;
        float l = 0.f;
#pragma unroll
        for (int p = 0; p < JSPLIT; ++p) l += g_lp[p * (H * NN) + row];
        sl[threadIdx.x] = 1.0f / l;
    }
    __syncthreads();
    const float* Pb = g_P + ((size_t)h * NN + (size_t)g * BM) * NN + j0;
    float4 acc = make_float4(0.f, 0.f, 0.f, 0.f);
#pragma unroll 8
    for (int i = 0; i < BM; ++i) {
        float4 x = *reinterpret_cast<const float4*>(Pb + (size_t)i * NN);
        float w = sl[i];
        acc.x += x.x * w; acc.y += x.y * w;
        acc.z += x.z * w; acc.w += x.w * w;
    }
    *reinterpret_cast<float4*>(g_bs + (size_t)hg * NN + j0) = acc;
}

// ---------------- block scan helper -----------------------------------------
__device__ __forceinline__ int blockScanExcl(int val, int t, int* wsum, int& total) {
    __syncthreads();
    int lane = t & 31, w = t >> 5;
    int x = val;
#pragma unroll
    for (int o = 1; o < 32; o <<= 1) {
        int y = __shfl_up_sync(0xFFFFFFFFu, x, o);
        if (lane >= o) x += y;
    }
    if (lane == 31) wsum[w] = x;
    __syncthreads();
    if (t < 8) {
        int y = wsum[t];
#pragma unroll
        for (int o = 1; o < 8; o <<= 1) {
            int z = __shfl_up_sync(0xFFu, y, o);
            if (t >= o) y += z;
        }
        wsum[t] = y;
    }
    __syncthreads();
    int base = (w > 0) ? wsum[w - 1] : 0;
    total = wsum[7];
    return base + x - val;
}

// ---------------- kernel C: top-k select + static + random -> index list ----
__global__ __launch_bounds__(256) void kC(uint32_t k1a, uint32_t k1b,
                                          uint32_t k2a, uint32_t k2b) {
    __shared__ uint32_t su[NN];
    __shared__ int hist[256];
    __shared__ int wsum[8];
    __shared__ int s_digit, s_rem;
    const int hg = blockIdx.x;
    const int g = hg % QG;
    const int t = threadIdx.x;

    const float* bs = g_bs + (size_t)hg * NN;
    for (int e = t; e < NN; e += 256) su[e] = __float_as_uint(bs[e]);
    __syncthreads();

    uint32_t pre = 0, preMask = 0;
    int rem = IC;
    for (int shift = 24; shift >= 0; shift -= 8) {
        hist[t] = 0;
        __syncthreads();
#pragma unroll
        for (int ee = 0; ee < 8; ++ee) {
            uint32_t u = su[t * 8 + ee];
            if ((u & preMask) == pre) atomicAdd(&hist[(u >> shift) & 255], 1);
        }
        __syncthreads();
        if (t == 0) {
            int cum = 0, d = 255;
            for (; d > 0; --d) {
                int c = hist[d];
                if (cum + c >= rem) break;
                cum += c;
            }
            s_digit = d;
            s_rem = rem - cum;
        }
        __syncthreads();
        pre |= ((uint32_t)s_digit) << shift;
        preMask |= 0xFFu << shift;
        rem = s_rem;
        __syncthreads();
    }
    const uint32_t v = pre;
    const int need_eq = rem;

    // rank among equals (ascending index, matching lax.top_k stability)
    int eqc = 0;
#pragma unroll
    for (int ee = 0; ee < 8; ++ee) eqc += (su[t * 8 + ee] == v) ? 1 : 0;
    int dummy;
    int eq_base = blockScanExcl(eqc, t, wsum, dummy);

    const int lo = g * BM + BM / 2 - WHALF;
    const int hi = g * BM + BM / 2 + WHALF;

    unsigned char lf[8];
    int fc = 0, eqrun = eq_base;
#pragma unroll
    for (int ee = 0; ee < 8; ++ee) {
        int j = t * 8 + ee;
        uint32_t u = su[j];
        bool topk = (u > v);
        if (u == v) { topk = topk || (eqrun < need_eq); ++eqrun; }
        bool stat = (j >= lo) && (j < hi);
        uint32_t ilin = (uint32_t)hg * NN + (uint32_t)j;
        uint32_t hb = tf_fold(k1a, k1b, 0u, ilin);
        uint32_t lb = tf_fold(k2a, k2b, 0u, ilin);
        bool rnd = (((hb % 100u) * 96u + (lb % 100u)) % 100u) == 0u;
        bool f = topk || stat || rnd;
        lf[ee] = f ? 1 : 0;
        fc += lf[ee];
    }
    int tot;
    int base = blockScanExcl(fc, t, wsum, tot);
    int* dst = g_idx + (size_t)hg * NN;
    int p = base;
#pragma unroll
    for (int ee = 0; ee < 8; ++ee)
        if (lf[ee]) dst[p++] = t * 8 + ee;
    if (t == 0) g_cnt[hg] = tot;
}

// ---------------- kernel D: sparse PV partials (split-K over key tiles) -----
// grid (384, KSPLIT), 256 thr, 49.4 KB smem, <=64 regs -> 4 CTA/SM.
__global__ __launch_bounds__(256, 4) void kD(const float* __restrict__ vin) {
    extern __shared__ float dynD[];
    float* sV = dynD;                    // 64*128
    float* sP = dynD + 64 * 128;         // 64*64 (broadcast reads: no pad)
    int* sIdx = reinterpret_cast<int*>(dynD + 64 * 128 + 64 * 64);

    const int hg = blockIdx.x;
    const int s = blockIdx.y;
    const int h = hg / QG, g = hg % QG;
    const int t = threadIdx.x;
    const int lane = t & 31;
    const int tg = t >> 5;               // warp id 0..7 -> rows tg*8..tg*8+7
    int cnt = g_cnt[hg];
    if (cnt < 1) cnt = 1;
    const int* idx = g_idx + (size_t)hg * NN;

    float acc[8][4];
#pragma unroll
    for (int r = 0; r < 8; ++r) {
        acc[r][0] = 0.f; acc[r][1] = 0.f; acc[r][2] = 0.f; acc[r][3] = 0.f;
    }
    float ls[8];
#pragma unroll
    for (int r = 0; r < 8; ++r) ls[r] = 0.f;

    const float* vb = vin + (size_t)h * NN * DD;
    const size_t prow0 = ((size_t)h * NN + (size_t)g * BM) * NN;

    for (int j0 = s * 64; j0 < cnt; j0 += KSPLIT * 64) {
        const int tl = min(64, cnt - j0);
        __syncthreads();
        if (t < 64) sIdx[t] = (t < tl) ? idx[j0 + t] : 0;
        __syncthreads();
        // gather P tile (zero padded columns)
        for (int e = t; e < 64 * 64; e += 256) {
            int ii = e >> 6, jj = e & 63;
            sP[ii * 64 + jj] = (jj < tl) ? g_P[prow0 + (size_t)ii * NN + sIdx[jj]] : 0.f;
        }
        // gather V tile rows
        for (int e = t; e < 64 * 32; e += 256) {
            int jj = e >> 5, c = e & 31;
            float4 val;
            if (jj < tl) val = reinterpret_cast<const float4*>(vb + (size_t)sIdx[jj] * DD)[c];
            else         val = make_float4(0.f, 0.f, 0.f, 0.f);
            reinterpret_cast<float4*>(sV)[jj * 32 + c] = val;
        }
        __syncthreads();

        const float* sProw = sP + tg * 8 * 64;
#pragma unroll 2
        for (int jj = 0; jj < 64; ++jj) {
            float4 v4 = *reinterpret_cast<const float4*>(sV + jj * 128 + lane * 4);
#pragma unroll
            for (int r = 0; r < 8; ++r) {
                float p = sProw[r * 64 + jj];     // broadcast across warp
                ls[r] += p;
                acc[r][0] += p * v4.x;
                acc[r][1] += p * v4.y;
                acc[r][2] += p * v4.z;
                acc[r][3] += p * v4.w;
            }
        }
    }

    float* ab = g_accD + ((size_t)hg * KSPLIT + s) * (BM * DD);
    float* lb = g_lsD + (hg * KSPLIT + s) * BM;
#pragma unroll
    for (int r = 0; r < 8; ++r) {
        int row = tg * 8 + r;
        *reinterpret_cast<float4*>(ab + row * DD + lane * 4) =
            make_float4(acc[r][0], acc[r][1], acc[r][2], acc[r][3]);
        if (lane == 0) lb[row] = ls[r];
    }
}

// ---------------- kernel E: combine kD partials + cache add -----------------
// grid 384, 256 thr. thread t: row = t>>2, 32-dim segment (t&3)*32.
__global__ __launch_bounds__(256) void kE(const float* __restrict__ cache,
                                          float* __restrict__ out) {
    const int hg = blockIdx.x;
    const int h = hg / QG, g = hg % QG;
    const int t = threadIdx.x;
    const int row = t >> 2;
    const int seg = (t & 3) * 32;

    const float* lb = g_lsD + hg * KSPLIT * BM;
    float lsum = 0.f;
#pragma unroll
    for (int s = 0; s < KSPLIT; ++s) lsum += lb[s * BM + row];
    const float inv = 1.0f / lsum;

    const float* ab = g_accD + (size_t)hg * KSPLIT * (BM * DD) + row * DD + seg;
    const size_t grow = (size_t)h * NN + (size_t)g * BM + row;
    const float* cr = cache + grow * DD + seg;
    float* orow = out + grow * DD + seg;

#pragma unroll
    for (int c = 0; c < 32; c += 4) {
        float4 a0 = *reinterpret_cast<const float4*>(ab + c);
        float4 a1 = *reinterpret_cast<const float4*>(ab + BM * DD + c);
        float4 a2 = *reinterpret_cast<const float4*>(ab + 2 * BM * DD + c);
        float4 cv = *reinterpret_cast<const float4*>(cr + c);
        float4 ov;
        ov.x = cv.x + (a0.x + a1.x + a2.x) * inv;
        ov.y = cv.y + (a0.y + a1.y + a2.y) * inv;
        ov.z = cv.z + (a0.z + a1.z + a2.z) * inv;
        ov.w = cv.w + (a0.w + a1.w + a2.w) * inv;
        *reinterpret_cast<float4*>(orow + c) = ov;
    }
}

// ---------------- launch -----------------------------------------------------
extern "C" void kernel_launch(void* const* d_in, const int* in_sizes, int n_in,
                              void* d_out, int out_size) {
    const float* q     = (const float*)d_in[0];
    const float* k     = (const float*)d_in[1];
    const float* v     = (const float*)d_in[2];
    const float* cache = (const float*)d_in[3];
    float* out = (float*)d_out;

    (void)in_sizes; (void)n_in; (void)out_size;

    cudaFuncSetAttribute(kAwm, cudaFuncAttributeMaxDynamicSharedMemorySize, SMEM_AWM);
    cudaFuncSetAttribute(kD, cudaFuncAttributeMaxDynamicSharedMemorySize, 49408);

    // JAX key(1) = (0,1); partitionable foldlike split -> k1, k2
    uint32_t k1a, k1b, k2a, k2b;
    tf2x32(0u, 1u, 0u, 0u, k1a, k1b);
    tf2x32(0u, 1u, 0u, 1u, k2a, k2b);

    dim3 gA(32, H, JSPLIT);
    kAwm<<<gA, 256, SMEM_AWM>>>(q, k);
    dim3 gB(H * QG, 2);
    kB<<<gB, 256>>>();
    kC<<<H * QG, 256>>>(k1a, k1b, k2a, k2b);
    dim3 gD(H * QG, KSPLIT);
    kD<<<gD, 256, 49408>>>(v);
    kE<<<H * QG, 256>>>(cache, out);
}